// round 6
// baseline (speedup 1.0000x reference)
#include <cuda_runtime.h>
#include <cstdint>
#include <cstddef>

#define TSTEPS 512
#define BATCH  128

// 192MB scratch for the input projection (static device array: allowed).
__device__ float g_Gx[(size_t)BATCH * TSTEPS * 768];

// ---- f32x2 helpers ----
typedef unsigned long long ull;
__device__ __forceinline__ ull pack2(float x, float y) {
    ull u; asm("mov.b64 %0, {%1,%2};" : "=l"(u) : "f"(x), "f"(y)); return u;
}
__device__ __forceinline__ void unpack2(ull u, float& x, float& y) {
    asm("mov.b64 {%0,%1}, %2;" : "=f"(x), "=f"(y) : "l"(u));
}
__device__ __forceinline__ void fma2(ull& d, ull a, ull b) {
    asm("fma.rn.f32x2 %0, %1, %2, %0;" : "+l"(d) : "l"(a), "l"(b));
}
__device__ __forceinline__ ull add2(ull a, ull b) {
    ull d; asm("add.rn.f32x2 %0, %1, %2;" : "=l"(d) : "l"(a), "l"(b)); return d;
}

// ---- cluster / mbarrier helpers ----
__device__ __forceinline__ uint32_t smem_u32(const void* p) {
    uint32_t a;
    asm("{ .reg .u64 t; cvta.to.shared.u64 t, %1; cvt.u32.u64 %0, t; }" : "=r"(a) : "l"(p));
    return a;
}
__device__ __forceinline__ uint32_t mapa_rank(uint32_t addr, uint32_t rank) {
    uint32_t r; asm("mapa.shared::cluster.u32 %0, %1, %2;" : "=r"(r) : "r"(addr), "r"(rank));
    return r;
}
__device__ __forceinline__ void st_cluster_u64(uint32_t addr, ull v) {
    asm volatile("st.shared::cluster.b64 [%0], %1;" :: "r"(addr), "l"(v));
}
__device__ __forceinline__ void cluster_sync() {
    asm volatile("barrier.cluster.arrive.aligned;" ::: "memory");
    asm volatile("barrier.cluster.wait.aligned;" ::: "memory");
}
__device__ __forceinline__ uint32_t cluster_rank() {
    uint32_t r; asm("mov.u32 %0, %%cluster_ctarank;" : "=r"(r)); return r;
}
__device__ __forceinline__ void mbar_init(uint32_t addr, uint32_t count) {
    asm volatile("mbarrier.init.shared.b64 [%0], %1;" :: "r"(addr), "r"(count) : "memory");
}
__device__ __forceinline__ void mbar_arrive_remote(uint32_t addr) {
    asm volatile("mbarrier.arrive.release.cluster.shared::cluster.b64 _, [%0];"
                 :: "r"(addr) : "memory");
}
__device__ __forceinline__ void mbar_wait(uint32_t addr, uint32_t parity) {
    uint32_t done = 0;
    do {
        asm volatile("{\n\t.reg .pred p;\n\t"
            "mbarrier.try_wait.parity.acquire.cluster.shared::cta.b64 p, [%1], %2, 0x989680;\n\t"
            "selp.b32 %0, 1, 0, p;\n\t}"
            : "=r"(done) : "r"(addr), "r"(parity) : "memory");
    } while (!done);
}

// fast activations
__device__ __forceinline__ float fast_sigmoid(float x) {
    return __fdividef(1.0f, 1.0f + __expf(-x));
}
__device__ __forceinline__ float fast_tanh(float x) {
    return 2.0f * __fdividef(1.0f, 1.0f + __expf(-2.0f * x)) - 1.0f;
}

// ============================================================================
// Stage 1: Gx[m][gate*256+n] = x[m] @ W[:256] + b.  BM=128 BN=64 BK=16.
// ============================================================================
__global__ __launch_bounds__(256) void proj_kernel(
    const float* __restrict__ x,
    const float* __restrict__ Wr, const float* __restrict__ br,
    const float* __restrict__ Wz, const float* __restrict__ bz,
    const float* __restrict__ Wc, const float* __restrict__ bc)
{
    const int mTile = blockIdx.x, nTile = blockIdx.y;
    const int gate = nTile >> 2, nGateBase = (nTile & 3) * 64;
    const float* W    = (gate == 0) ? Wr : ((gate == 1) ? Wz : Wc);
    const float* bias = (gate == 0) ? br : ((gate == 1) ? bz : bc);

    __shared__ float As[16][132];
    __shared__ float Ws[16][64];

    const int tid = threadIdx.x;
    const int tx = tid & 15, ty = tid >> 4;
    const int mBase = mTile * 128;

    ull acc[4][4];
    #pragma unroll
    for (int i = 0; i < 4; i++)
        #pragma unroll
        for (int jj = 0; jj < 4; jj++) acc[i][jj] = 0ull;

    float bv[4];
    #pragma unroll
    for (int jj = 0; jj < 4; jj++) bv[jj] = bias[nGateBase + tx * 4 + jj];

    for (int k0 = 0; k0 < 256; k0 += 16) {
        __syncthreads();
        #pragma unroll
        for (int q = 0; q < 2; q++) {
            int idx = tid + q * 256, row = idx >> 2, c4 = idx & 3;
            float4 v = *reinterpret_cast<const float4*>(
                &x[(size_t)(mBase + row) * 256 + k0 + c4 * 4]);
            As[c4 * 4 + 0][row] = v.x; As[c4 * 4 + 1][row] = v.y;
            As[c4 * 4 + 2][row] = v.z; As[c4 * 4 + 3][row] = v.w;
        }
        {
            int k = tid >> 4, n4 = (tid & 15) * 4;
            *reinterpret_cast<float4*>(&Ws[k][n4]) =
                *reinterpret_cast<const float4*>(&W[(size_t)(k0 + k) * 256 + nGateBase + n4]);
        }
        __syncthreads();

        #pragma unroll
        for (int k = 0; k < 16; k++) {
            const ull* ap = reinterpret_cast<const ull*>(&As[k][ty * 8]);
            ull a0 = ap[0], a1 = ap[1], a2 = ap[2], a3 = ap[3];
            #pragma unroll
            for (int jj = 0; jj < 4; jj++) {
                float w = Ws[k][tx * 4 + jj];
                ull w2 = pack2(w, w);
                fma2(acc[0][jj], a0, w2); fma2(acc[1][jj], a1, w2);
                fma2(acc[2][jj], a2, w2); fma2(acc[3][jj], a3, w2);
            }
        }
    }

    const int nOut = gate * 256 + nGateBase + tx * 4;
    #pragma unroll
    for (int rp = 0; rp < 4; rp++) {
        float r0[4], r1[4];
        #pragma unroll
        for (int jj = 0; jj < 4; jj++) {
            unpack2(acc[rp][jj], r0[jj], r1[jj]);
            r0[jj] += bv[jj]; r1[jj] += bv[jj];
        }
        int m0 = mBase + ty * 8 + rp * 2;
        *reinterpret_cast<float4*>(&g_Gx[(size_t)m0 * 768 + nOut]) =
            make_float4(r0[0], r0[1], r0[2], r0[3]);
        *reinterpret_cast<float4*>(&g_Gx[(size_t)(m0 + 1) * 768 + nOut]) =
            make_float4(r1[0], r1[1], r1[2], r1[3]);
    }
}

// ============================================================================
// Stage 2: recurrence. 32 clusters x 8 CTAs, 4 rows/cluster, 2 CTAs/SM.
// Step order: GEMM_r -> push r*h (hidden under GEMM_z) -> GEMM_z -> GEMM_c.
// mbarrier sync (512 arrivals), double-buffered hT/rhT.
// ============================================================================
struct __align__(16) RecSmem {
    float wcT[256][32];        // Wc h-part [k][c]                      32KB
    float hT[2][256][4];       // h transposed [buf][k][row]             8KB
    float rhT[2][256][4];      // r*h transposed                         8KB
    ull   z2[2][32];           // z gate [rowpair][col]                 .5KB
    ull   red_r[8][2][32];     // split-K partials [kg][rp][col]         4KB
    ull   red_z[8][2][32];     //                                        4KB
    ull   red_c[8][2][32];     //                                        4KB
    unsigned long long mbar[2];  // [0]=h_bar, [1]=rh_bar
};

__global__ __launch_bounds__(256, 2) __cluster_dims__(8, 1, 1)
void rec_kernel(const float* __restrict__ h0,
                const float* __restrict__ Wr,
                const float* __restrict__ Wz,
                const float* __restrict__ Wc,
                float* __restrict__ out)
{
    extern __shared__ char smem_raw[];
    RecSmem& S = *reinterpret_cast<RecSmem*>(smem_raw);

    const int tid = threadIdx.x;
    const int j = (int)cluster_rank();       // 0..7
    const int b0 = (blockIdx.x >> 3) * 4;    // first batch row of cluster

    // roles: all GEMMs: 1 col, 8-way split-K of 32; epis: tid<64
    const int col = tid & 31, kg = tid >> 5;
    const int ec  = tid & 31, erp = (tid >> 5) & 1;   // valid for tid<64
    const int kb  = kg * 32;

    // ---- register weights for r and z gates (1 col x 32 k each) ----
    float w1r[32], w1z[32];
    {
        const int c = j * 32 + col;
        #pragma unroll
        for (int kk = 0; kk < 32; kk++) {
            w1r[kk] = Wr[(size_t)(256 + kb + kk) * 256 + c];
            w1z[kk] = Wz[(size_t)(256 + kb + kk) * 256 + c];
        }
    }

    // ---- SMEM init: Wc tile, h state (buffer 0), mbarriers ----
    for (int idx = tid; idx < 256 * 32; idx += 256) {
        int k = idx >> 5, c = idx & 31;
        S.wcT[k][c] = Wc[(size_t)(256 + k) * 256 + j * 32 + c];
    }
    for (int idx = tid; idx < 1024; idx += 256) {
        int k = idx >> 2, r = idx & 3;
        S.hT[0][k][r] = h0[(size_t)(b0 + r) * 256 + k];
    }
    if (tid == 0) {
        mbar_init(smem_u32(&S.mbar[0]), 512);   // h_bar: 64 thr x 8 CTAs
        mbar_init(smem_u32(&S.mbar[1]), 512);   // rh_bar
    }
    __syncthreads();
    cluster_sync();   // peers' init visible before any remote op

    // ---- peer DSMEM addresses ----
    const uint32_t base = smem_u32(&S);
    uint32_t peer[8], peer_hbar[8], peer_rhbar[8];
    const uint32_t hbar_l  = smem_u32(&S.mbar[0]);
    const uint32_t rhbar_l = smem_u32(&S.mbar[1]);
    #pragma unroll
    for (int rk = 0; rk < 8; rk++) {
        peer[rk]       = mapa_rank(base, (uint32_t)rk);
        peer_hbar[rk]  = mapa_rank(hbar_l, (uint32_t)rk);
        peer_rhbar[rk] = mapa_rank(rhbar_l, (uint32_t)rk);
    }
    const uint32_t off_h[2]  = { (uint32_t)(smem_u32(&S.hT[0][0][0]) - base),
                                 (uint32_t)(smem_u32(&S.hT[1][0][0]) - base) };
    const uint32_t off_rh[2] = { (uint32_t)(smem_u32(&S.rhT[0][0][0]) - base),
                                 (uint32_t)(smem_u32(&S.rhT[1][0][0]) - base) };

    // ---- Gx address bases for epi threads (tid<64) ----
    const size_t bR0 = (size_t)(b0 + 2 * erp)     * TSTEPS * 768 + j * 32 + ec;
    const size_t bR1 = (size_t)(b0 + 2 * erp + 1) * TSTEPS * 768 + j * 32 + ec;

    #pragma unroll 1
    for (int t = 0; t < TSTEPS; t++) {
        const int buf = t & 1;

        // wait: hT[buf] fully pushed by all peers during step t-1
        if (t > 0) mbar_wait(hbar_l, (uint32_t)((t - 1) & 1));

        // Gx loads for this step (hidden under GEMM_r)
        float gR0 = 0.f, gR1 = 0.f, gZ0 = 0.f, gZ1 = 0.f, gC0 = 0.f, gC1 = 0.f;
        if (tid < 64) {
            const size_t to = (size_t)t * 768;
            gR0 = g_Gx[bR0 + to];       gR1 = g_Gx[bR1 + to];
            gZ0 = g_Gx[bR0 + to + 256]; gZ1 = g_Gx[bR1 + to + 256];
            gC0 = g_Gx[bR0 + to + 512]; gC1 = g_Gx[bR1 + to + 512];
        }

        // -- GEMM_r: h @ Wh_r --
        {
            ull a0 = 0, a1 = 0;
            #pragma unroll
            for (int kk = 0; kk < 32; kk++) {
                ulonglong2 hp = *reinterpret_cast<const ulonglong2*>(&S.hT[buf][kb + kk][0]);
                ull w2 = pack2(w1r[kk], w1r[kk]);
                fma2(a0, hp.x, w2); fma2(a1, hp.y, w2);
            }
            S.red_r[kg][0][col] = a0; S.red_r[kg][1][col] = a1;
        }
        __syncthreads();

        // -- epi_r (tid<64): sigmoid r, push r*h + arrive rh_bar --
        if (tid < 64) {
            ull s = S.red_r[0][erp][ec];
            #pragma unroll
            for (int g = 1; g < 8; g++) s = add2(s, S.red_r[g][erp][ec]);
            float lo, hi; unpack2(s, lo, hi);
            float r0 = fast_sigmoid(lo + gR0), r1 = fast_sigmoid(hi + gR1);
            int k = j * 32 + ec;
            ull h2 = *reinterpret_cast<const ull*>(&S.hT[buf][k][2 * erp]);
            float ha, hb; unpack2(h2, ha, hb);
            ull rh2 = pack2(r0 * ha, r1 * hb);
            uint32_t o = off_rh[buf] + (uint32_t)((k * 4 + 2 * erp) * 4);
            #pragma unroll
            for (int rk = 0; rk < 8; rk++) st_cluster_u64(peer[rk] + o, rh2);
            #pragma unroll
            for (int rk = 0; rk < 8; rk++) mbar_arrive_remote(peer_rhbar[rk]);
        }

        // -- GEMM_z: h @ Wh_z (overlaps the r*h exchange) --
        {
            ull a0 = 0, a1 = 0;
            #pragma unroll
            for (int kk = 0; kk < 32; kk++) {
                ulonglong2 hp = *reinterpret_cast<const ulonglong2*>(&S.hT[buf][kb + kk][0]);
                ull w2 = pack2(w1z[kk], w1z[kk]);
                fma2(a0, hp.x, w2); fma2(a1, hp.y, w2);
            }
            S.red_z[kg][0][col] = a0; S.red_z[kg][1][col] = a1;
        }
        __syncthreads();

        // -- epi_z (tid<64): sigmoid z to smem --
        if (tid < 64) {
            ull s = S.red_z[0][erp][ec];
            #pragma unroll
            for (int g = 1; g < 8; g++) s = add2(s, S.red_z[g][erp][ec]);
            float lo, hi; unpack2(s, lo, hi);
            S.z2[erp][ec] = pack2(fast_sigmoid(lo + gZ0), fast_sigmoid(hi + gZ1));
        }

        // wait: rhT[buf] fully pushed by all peers (this step)
        mbar_wait(rhbar_l, (uint32_t)(t & 1));

        // -- GEMM_c: (r*h) @ Wh_c (Wc from SMEM) --
        {
            ull a0 = 0, a1 = 0;
            #pragma unroll
            for (int kk = 0; kk < 32; kk++) {
                ulonglong2 hp = *reinterpret_cast<const ulonglong2*>(&S.rhT[buf][kb + kk][0]);
                float w = S.wcT[kb + kk][col];
                ull w2 = pack2(w, w);
                fma2(a0, hp.x, w2); fma2(a1, hp.y, w2);
            }
            S.red_c[kg][0][col] = a0; S.red_c[kg][1][col] = a1;
        }
        __syncthreads();

        // -- epi_c (tid<64): candidate, h update, output, push h_new + arrive --
        if (tid < 64) {
            ull s = S.red_c[0][erp][ec];
            #pragma unroll
            for (int g = 1; g < 8; g++) s = add2(s, S.red_c[g][erp][ec]);
            float lo, hi; unpack2(s, lo, hi);
            float c0 = fast_tanh(lo + gC0), c1 = fast_tanh(hi + gC1);
            float z0, z1; unpack2(S.z2[erp][ec], z0, z1);
            int k = j * 32 + ec;
            ull h2 = *reinterpret_cast<const ull*>(&S.hT[buf][k][2 * erp]);
            float ha, hb; unpack2(h2, ha, hb);
            float hn0 = ha + z0 * (c0 - ha);
            float hn1 = hb + z1 * (c1 - hb);
            out[((size_t)(b0 + 2 * erp) * TSTEPS + t) * 256 + k] = hn0;
            out[((size_t)(b0 + 2 * erp + 1) * TSTEPS + t) * 256 + k] = hn1;
            ull hn2 = pack2(hn0, hn1);
            uint32_t o = off_h[buf ^ 1] + (uint32_t)((k * 4 + 2 * erp) * 4);
            #pragma unroll
            for (int rk = 0; rk < 8; rk++) st_cluster_u64(peer[rk] + o, hn2);
            #pragma unroll
            for (int rk = 0; rk < 8; rk++) mbar_arrive_remote(peer_hbar[rk]);
        }
    }

    cluster_sync();   // no CTA exits while remote ops may still target it
}

extern "C" void kernel_launch(void* const* d_in, const int* in_sizes, int n_in,
                              void* d_out, int out_size) {
    const float* x  = (const float*)d_in[0];
    const float* h0 = (const float*)d_in[1];
    const float* Wr = (const float*)d_in[2];
    const float* br = (const float*)d_in[3];
    const float* Wz = (const float*)d_in[4];
    const float* bz = (const float*)d_in[5];
    const float* Wc = (const float*)d_in[6];
    const float* bc = (const float*)d_in[7];
    float* out = (float*)d_out;

    cudaFuncSetAttribute(rec_kernel, cudaFuncAttributeMaxDynamicSharedMemorySize,
                         (int)sizeof(RecSmem));

    proj_kernel<<<dim3(512, 12), 256>>>(x, Wr, br, Wz, bz, Wc, bc);
    rec_kernel<<<256, 256, sizeof(RecSmem)>>>(h0, Wr, Wz, Wc, out);
}

// round 7
// speedup vs baseline: 1.4957x; 1.4957x over previous
#include <cuda_runtime.h>
#include <cstdint>
#include <cstddef>

#define TSTEPS 512
#define BATCH  128

// 192MB scratch for the input projection (static device array: allowed).
__device__ float g_Gx[(size_t)BATCH * TSTEPS * 768];

// ---- f32x2 helpers ----
typedef unsigned long long ull;
__device__ __forceinline__ ull pack2(float x, float y) {
    ull u; asm("mov.b64 %0, {%1,%2};" : "=l"(u) : "f"(x), "f"(y)); return u;
}
__device__ __forceinline__ void unpack2(ull u, float& x, float& y) {
    asm("mov.b64 {%0,%1}, %2;" : "=f"(x), "=f"(y) : "l"(u));
}
__device__ __forceinline__ void fma2(ull& d, ull a, ull b) {
    asm("fma.rn.f32x2 %0, %1, %2, %0;" : "+l"(d) : "l"(a), "l"(b));
}
__device__ __forceinline__ ull add2(ull a, ull b) {
    ull d; asm("add.rn.f32x2 %0, %1, %2;" : "=l"(d) : "l"(a), "l"(b)); return d;
}

// ---- cluster helpers ----
__device__ __forceinline__ uint32_t smem_u32(const void* p) {
    uint32_t a;
    asm("{ .reg .u64 t; cvta.to.shared.u64 t, %1; cvt.u32.u64 %0, t; }" : "=r"(a) : "l"(p));
    return a;
}
__device__ __forceinline__ uint32_t mapa_rank(uint32_t addr, uint32_t rank) {
    uint32_t r; asm("mapa.shared::cluster.u32 %0, %1, %2;" : "=r"(r) : "r"(addr), "r"(rank));
    return r;
}
__device__ __forceinline__ void st_cluster_u64(uint32_t addr, ull v) {
    asm volatile("st.shared::cluster.b64 [%0], %1;" :: "r"(addr), "l"(v));
}
__device__ __forceinline__ void cluster_arrive() {
    asm volatile("barrier.cluster.arrive.aligned;" ::: "memory");
}
__device__ __forceinline__ void cluster_wait() {
    asm volatile("barrier.cluster.wait.aligned;" ::: "memory");
}
__device__ __forceinline__ void cluster_sync() {
    cluster_arrive(); cluster_wait();
}
__device__ __forceinline__ uint32_t cluster_rank() {
    uint32_t r; asm("mov.u32 %0, %%cluster_ctarank;" : "=r"(r)); return r;
}

// fast activations
__device__ __forceinline__ float fast_sigmoid(float x) {
    return __fdividef(1.0f, 1.0f + __expf(-x));
}
__device__ __forceinline__ float fast_tanh(float x) {
    return 2.0f * __fdividef(1.0f, 1.0f + __expf(-2.0f * x)) - 1.0f;
}

// ============================================================================
// Stage 1: Gx[m][gate*256+n] = x[m] @ W[:256] + b.  BM=128 BN=64 BK=16.
// ============================================================================
__global__ __launch_bounds__(256) void proj_kernel(
    const float* __restrict__ x,
    const float* __restrict__ Wr, const float* __restrict__ br,
    const float* __restrict__ Wz, const float* __restrict__ bz,
    const float* __restrict__ Wc, const float* __restrict__ bc)
{
    const int mTile = blockIdx.x, nTile = blockIdx.y;
    const int gate = nTile >> 2, nGateBase = (nTile & 3) * 64;
    const float* W    = (gate == 0) ? Wr : ((gate == 1) ? Wz : Wc);
    const float* bias = (gate == 0) ? br : ((gate == 1) ? bz : bc);

    __shared__ float As[16][132];
    __shared__ float Ws[16][64];

    const int tid = threadIdx.x;
    const int tx = tid & 15, ty = tid >> 4;
    const int mBase = mTile * 128;

    ull acc[4][4];
    #pragma unroll
    for (int i = 0; i < 4; i++)
        #pragma unroll
        for (int jj = 0; jj < 4; jj++) acc[i][jj] = 0ull;

    float bv[4];
    #pragma unroll
    for (int jj = 0; jj < 4; jj++) bv[jj] = bias[nGateBase + tx * 4 + jj];

    for (int k0 = 0; k0 < 256; k0 += 16) {
        __syncthreads();
        #pragma unroll
        for (int q = 0; q < 2; q++) {
            int idx = tid + q * 256, row = idx >> 2, c4 = idx & 3;
            float4 v = *reinterpret_cast<const float4*>(
                &x[(size_t)(mBase + row) * 256 + k0 + c4 * 4]);
            As[c4 * 4 + 0][row] = v.x; As[c4 * 4 + 1][row] = v.y;
            As[c4 * 4 + 2][row] = v.z; As[c4 * 4 + 3][row] = v.w;
        }
        {
            int k = tid >> 4, n4 = (tid & 15) * 4;
            *reinterpret_cast<float4*>(&Ws[k][n4]) =
                *reinterpret_cast<const float4*>(&W[(size_t)(k0 + k) * 256 + nGateBase + n4]);
        }
        __syncthreads();

        #pragma unroll
        for (int k = 0; k < 16; k++) {
            const ull* ap = reinterpret_cast<const ull*>(&As[k][ty * 8]);
            ull a0 = ap[0], a1 = ap[1], a2 = ap[2], a3 = ap[3];
            #pragma unroll
            for (int jj = 0; jj < 4; jj++) {
                float w = Ws[k][tx * 4 + jj];
                ull w2 = pack2(w, w);
                fma2(acc[0][jj], a0, w2); fma2(acc[1][jj], a1, w2);
                fma2(acc[2][jj], a2, w2); fma2(acc[3][jj], a3, w2);
            }
        }
    }

    const int nOut = gate * 256 + nGateBase + tx * 4;
    #pragma unroll
    for (int rp = 0; rp < 4; rp++) {
        float r0[4], r1[4];
        #pragma unroll
        for (int jj = 0; jj < 4; jj++) {
            unpack2(acc[rp][jj], r0[jj], r1[jj]);
            r0[jj] += bv[jj]; r1[jj] += bv[jj];
        }
        int m0 = mBase + ty * 8 + rp * 2;
        *reinterpret_cast<float4*>(&g_Gx[(size_t)m0 * 768 + nOut]) =
            make_float4(r0[0], r0[1], r0[2], r0[3]);
        *reinterpret_cast<float4*>(&g_Gx[(size_t)(m0 + 1) * 768 + nOut]) =
            make_float4(r1[0], r1[1], r1[2], r1[3]);
    }
}

// ============================================================================
// Stage 2: recurrence. 32 clusters x 8 CTAs, 4 rows/cluster, 2 CTAs/SM.
// Split hardware cluster barriers (arrive/wait) hide the two DSMEM exchanges:
//   GxLDG -> WAIT(h) -> GEMM_r -> epi_r(push rh, ARRIVE) -> GEMM_z -> epi_z
//   -> WAIT(rh) -> GEMM_c -> epi_c(push h', ARRIVE)
// ============================================================================
struct __align__(16) RecSmem {
    float wcT[256][32];        // Wc h-part [k][c]                      32KB
    float hT[2][256][4];       // h transposed [buf][k][row]             8KB
    float rhT[256][4];         // r*h transposed (single buffer: safe)   4KB
    ull   z2[2][32];           // z gate [rowpair][col]                 .5KB
    ull   red_r[8][2][32];     // split-K partials [kg][rp][col]         4KB
    ull   red_z[8][2][32];     //                                        4KB
    ull   red_c[8][2][32];     //                                        4KB
};

__global__ __launch_bounds__(256, 2) __cluster_dims__(8, 1, 1)
void rec_kernel(const float* __restrict__ h0,
                const float* __restrict__ Wr,
                const float* __restrict__ Wz,
                const float* __restrict__ Wc,
                float* __restrict__ out)
{
    extern __shared__ char smem_raw[];
    RecSmem& S = *reinterpret_cast<RecSmem*>(smem_raw);

    const int tid = threadIdx.x;
    const int j = (int)cluster_rank();       // 0..7
    const int b0 = (blockIdx.x >> 3) * 4;    // first batch row of cluster

    // roles: GEMMs: 1 col, 8-way split-K of 32; epis: tid<64
    const int col = tid & 31, kg = tid >> 5;
    const int ec  = tid & 31, erp = (tid >> 5) & 1;   // valid for tid<64
    const int kb  = kg * 32;

    // ---- register weights for r and z gates (1 col x 32 k each) ----
    float w1r[32], w1z[32];
    {
        const int c = j * 32 + col;
        #pragma unroll
        for (int kk = 0; kk < 32; kk++) {
            w1r[kk] = Wr[(size_t)(256 + kb + kk) * 256 + c];
            w1z[kk] = Wz[(size_t)(256 + kb + kk) * 256 + c];
        }
    }

    // ---- SMEM init: Wc tile, h state (buffer 0) ----
    for (int idx = tid; idx < 256 * 32; idx += 256) {
        int k = idx >> 5, c = idx & 31;
        S.wcT[k][c] = Wc[(size_t)(256 + k) * 256 + j * 32 + c];
    }
    for (int idx = tid; idx < 1024; idx += 256) {
        int k = idx >> 2, r = idx & 3;
        S.hT[0][k][r] = h0[(size_t)(b0 + r) * 256 + k];
    }
    __syncthreads();
    cluster_sync();   // peers' hT init visible before any remote op

    // ---- peer DSMEM addresses ----
    const uint32_t base = smem_u32(&S);
    uint32_t peer[8];
    #pragma unroll
    for (int rk = 0; rk < 8; rk++) peer[rk] = mapa_rank(base, (uint32_t)rk);
    const uint32_t off_h[2]  = { (uint32_t)(smem_u32(&S.hT[0][0][0]) - base),
                                 (uint32_t)(smem_u32(&S.hT[1][0][0]) - base) };
    const uint32_t off_rh    = (uint32_t)(smem_u32(&S.rhT[0][0]) - base);

    // ---- Gx address bases for epi threads (tid<64) ----
    const size_t bR0 = (size_t)(b0 + 2 * erp)     * TSTEPS * 768 + j * 32 + ec;
    const size_t bR1 = (size_t)(b0 + 2 * erp + 1) * TSTEPS * 768 + j * 32 + ec;

    #pragma unroll 1
    for (int t = 0; t < TSTEPS; t++) {
        const int buf = t & 1;

        // Gx loads for this step FIRST: their DRAM latency overlaps the wait
        float gR0 = 0.f, gR1 = 0.f, gZ0 = 0.f, gZ1 = 0.f, gC0 = 0.f, gC1 = 0.f;
        if (tid < 64) {
            const size_t to = (size_t)t * 768;
            gR0 = g_Gx[bR0 + to];       gR1 = g_Gx[bR1 + to];
            gZ0 = g_Gx[bR0 + to + 256]; gZ1 = g_Gx[bR1 + to + 256];
            gC0 = g_Gx[bR0 + to + 512]; gC1 = g_Gx[bR1 + to + 512];
        }

        // WAIT2: h(t) pushed by all peers at end of step t-1
        if (t > 0) cluster_wait();

        // -- GEMM_r: h @ Wh_r --
        {
            ull a0 = 0, a1 = 0;
            #pragma unroll
            for (int kk = 0; kk < 32; kk++) {
                ulonglong2 hp = *reinterpret_cast<const ulonglong2*>(&S.hT[buf][kb + kk][0]);
                ull w2 = pack2(w1r[kk], w1r[kk]);
                fma2(a0, hp.x, w2); fma2(a1, hp.y, w2);
            }
            S.red_r[kg][0][col] = a0; S.red_r[kg][1][col] = a1;
        }
        __syncthreads();

        // -- epi_r (tid<64): sigmoid r, push r*h --
        if (tid < 64) {
            ull s = S.red_r[0][erp][ec];
            #pragma unroll
            for (int g = 1; g < 8; g++) s = add2(s, S.red_r[g][erp][ec]);
            float lo, hi; unpack2(s, lo, hi);
            float r0 = fast_sigmoid(lo + gR0), r1 = fast_sigmoid(hi + gR1);
            int k = j * 32 + ec;
            ull h2 = *reinterpret_cast<const ull*>(&S.hT[buf][k][2 * erp]);
            float ha, hb; unpack2(h2, ha, hb);
            ull rh2 = pack2(r0 * ha, r1 * hb);
            uint32_t o = off_rh + (uint32_t)((k * 4 + 2 * erp) * 4);
            #pragma unroll
            for (int rk = 0; rk < 8; rk++) st_cluster_u64(peer[rk] + o, rh2);
        }
        // ARRIVE1: rh pushes issued (release); propagation hides under GEMM_z
        cluster_arrive();

        // -- GEMM_z: h @ Wh_z (overlaps the r*h exchange + barrier) --
        {
            ull a0 = 0, a1 = 0;
            #pragma unroll
            for (int kk = 0; kk < 32; kk++) {
                ulonglong2 hp = *reinterpret_cast<const ulonglong2*>(&S.hT[buf][kb + kk][0]);
                ull w2 = pack2(w1z[kk], w1z[kk]);
                fma2(a0, hp.x, w2); fma2(a1, hp.y, w2);
            }
            S.red_z[kg][0][col] = a0; S.red_z[kg][1][col] = a1;
        }
        __syncthreads();

        // -- epi_z (tid<64): sigmoid z to smem --
        if (tid < 64) {
            ull s = S.red_z[0][erp][ec];
            #pragma unroll
            for (int g = 1; g < 8; g++) s = add2(s, S.red_z[g][erp][ec]);
            float lo, hi; unpack2(s, lo, hi);
            S.z2[erp][ec] = pack2(fast_sigmoid(lo + gZ0), fast_sigmoid(hi + gZ1));
        }

        // WAIT1: rhT complete from all peers (mostly satisfied already)
        cluster_wait();

        // -- GEMM_c: (r*h) @ Wh_c (Wc from SMEM) --
        {
            ull a0 = 0, a1 = 0;
            #pragma unroll
            for (int kk = 0; kk < 32; kk++) {
                ulonglong2 hp = *reinterpret_cast<const ulonglong2*>(&S.rhT[kb + kk][0]);
                float w = S.wcT[kb + kk][col];
                ull w2 = pack2(w, w);
                fma2(a0, hp.x, w2); fma2(a1, hp.y, w2);
            }
            S.red_c[kg][0][col] = a0; S.red_c[kg][1][col] = a1;
        }
        __syncthreads();

        // -- epi_c (tid<64): candidate, h update, output, push h(t+1) --
        if (tid < 64) {
            ull s = S.red_c[0][erp][ec];
            #pragma unroll
            for (int g = 1; g < 8; g++) s = add2(s, S.red_c[g][erp][ec]);
            float lo, hi; unpack2(s, lo, hi);
            float c0 = fast_tanh(lo + gC0), c1 = fast_tanh(hi + gC1);
            float z0, z1; unpack2(S.z2[erp][ec], z0, z1);
            int k = j * 32 + ec;
            ull h2 = *reinterpret_cast<const ull*>(&S.hT[buf][k][2 * erp]);
            float ha, hb; unpack2(h2, ha, hb);
            float hn0 = ha + z0 * (c0 - ha);
            float hn1 = hb + z1 * (c1 - hb);
            out[((size_t)(b0 + 2 * erp) * TSTEPS + t) * 256 + k] = hn0;
            out[((size_t)(b0 + 2 * erp + 1) * TSTEPS + t) * 256 + k] = hn1;
            ull hn2 = pack2(hn0, hn1);
            uint32_t o = off_h[buf ^ 1] + (uint32_t)((k * 4 + 2 * erp) * 4);
            #pragma unroll
            for (int rk = 0; rk < 8; rk++) st_cluster_u64(peer[rk] + o, hn2);
        }
        // ARRIVE2: h(t+1) pushes issued; next iteration's Gx LDGs + wait consume it
        cluster_arrive();
    }

    // consume the final ARRIVE2 so no CTA exits with peer pushes in flight
    cluster_wait();
}

extern "C" void kernel_launch(void* const* d_in, const int* in_sizes, int n_in,
                              void* d_out, int out_size) {
    const float* x  = (const float*)d_in[0];
    const float* h0 = (const float*)d_in[1];
    const float* Wr = (const float*)d_in[2];
    const float* br = (const float*)d_in[3];
    const float* Wz = (const float*)d_in[4];
    const float* bz = (const float*)d_in[5];
    const float* Wc = (const float*)d_in[6];
    const float* bc = (const float*)d_in[7];
    float* out = (float*)d_out;

    cudaFuncSetAttribute(rec_kernel, cudaFuncAttributeMaxDynamicSharedMemorySize,
                         (int)sizeof(RecSmem));

    proj_kernel<<<dim3(512, 12), 256>>>(x, Wr, br, Wz, bz, Wc, bc);
    rec_kernel<<<256, 256, sizeof(RecSmem)>>>(h0, Wr, Wz, Wc, out);
}